// round 11
// baseline (speedup 1.0000x reference)
#include <cuda_runtime.h>
#include <cuda_bf16.h>

// NeighborSearch_batch via 33x33 slotted grid (data + queries), 3 launches.
// Query kernel: per-CTA dense compaction of 8 cells' query slots; 4-lane
// groups per query; lane-private accept regions (no ballot chain);
// rank-selection emit (set-based -> deterministic, sorted).
// B=8, n=9225, m=4096, d=2, r=0.03.
// Output (float32): neighbors_index [B,m,64] then row_splits [B,m+1].

#define BATCH  8
#define NPTS   9225
#define NQ     4096
#define MAXN   64
#define GRIDW  33
#define NCELLS (GRIDW * GRIDW)        // 1089
#define SLOTC  48                     // data slots/cell  (lambda 8.5)
#define SLOTQ  32                     // query slots/cell (lambda 3.8)
#define CPC    8                      // cells per query-CTA (1089 CTAs total)
#define RCAP   48                     // per-lane accept region (u16 entries)
#define RSTR   50                     // region stride in u16 (25 words: odd)

// zero-initialized at module load; counters re-zeroed at end of each run
__device__ int    g_ccnt  [BATCH * NCELLS];
__device__ int    g_qcnt  [BATCH * NCELLS];
__device__ float4 g_slots [BATCH * NCELLS * SLOTC];  // (x, y, dn, idx bits)
__device__ float4 g_qslots[BATCH * NCELLS * SLOTQ];  // (x, y, qn, idx bits)
__device__ int    g_counts[BATCH * NQ];

__device__ __forceinline__ int clampi(int v, int lo, int hi) {
    return v < lo ? lo : (v > hi ? hi : v);
}

// ---- launch 1: scatter data AND queries into slotted cells ----
__global__ void scatter_kernel(const float* __restrict__ data,
                               const float* __restrict__ queries)
{
    const int gt = blockIdx.x * blockDim.x + threadIdx.x;
    if (gt < BATCH * NPTS) {
        const int b = gt / NPTS;
        const int j = gt - b * NPTS;
        const float2 pf = ((const float2*)data)[gt];
        // dn = RN(RN(x*x) + RN(y*y))  (matches jnp.sum(data*data))
        const float nn = __fadd_rn(__fmul_rn(pf.x, pf.x), __fmul_rn(pf.y, pf.y));
        const int cx = clampi((int)(pf.x * (float)GRIDW), 0, GRIDW - 1);
        const int cy = clampi((int)(pf.y * (float)GRIDW), 0, GRIDW - 1);
        const int c = b * NCELLS + cy * GRIDW + cx;
        const int pos = atomicAdd(&g_ccnt[c], 1);
        if (pos < SLOTC)
            g_slots[(size_t)c * SLOTC + pos] = make_float4(pf.x, pf.y, nn, __int_as_float(j));
    }
    if (gt < BATCH * NQ) {
        const int b = gt >> 12;
        const int j = gt & (NQ - 1);
        const float2 qf = ((const float2*)queries)[gt];
        const float nn = __fadd_rn(__fmul_rn(qf.x, qf.x), __fmul_rn(qf.y, qf.y));
        const int cx = clampi((int)(qf.x * (float)GRIDW), 0, GRIDW - 1);
        const int cy = clampi((int)(qf.y * (float)GRIDW), 0, GRIDW - 1);
        const int c = b * NCELLS + cy * GRIDW + cx;
        const int pos = atomicAdd(&g_qcnt[c], 1);
        if (pos < SLOTQ)
            g_qslots[(size_t)c * SLOTQ + pos] = make_float4(qf.x, qf.y, nn, __int_as_float(j));
    }
}

// ---- launch 2: query kernel ----
// CTA covers CPC=8 consecutive cells; compacts their query slots into a
// dense list; 4-lane group per query; lane-private accept regions.
__global__ void __launch_bounds__(128)
query_kernel(const float* __restrict__ radius,
             float* __restrict__ nbr_idx)
{
    __shared__ int            s_qp [CPC + 1];          // query prefix per cell
    __shared__ int            s_q  [CPC * SLOTQ];      // dense (e<<5)|slot
    __shared__ unsigned short s_reg[128 * RSTR];       // lane-private regions

    const int tid   = threadIdx.x;
    const int sub   = tid & 3;
    const int group = tid >> 2;          // 0..31
    const int tb    = tid & ~3;          // first tid of my group
    const int lb    = (tid & 31) & ~3;   // first lane of my group (in warp)

    const int cell0 = blockIdx.x * CPC;

    // cell query counts + serial prefix (CPC=8: trivial)
    if (tid == 0) {
        int run = 0;
        #pragma unroll
        for (int e = 0; e < CPC; ++e) {
            s_qp[e] = run;
            int v = g_qcnt[cell0 + e];
            run += (v < SLOTQ ? v : SLOTQ);
        }
        s_qp[CPC] = run;
    }
    __syncthreads();
    const int ncta = s_qp[CPC];
    if (ncta == 0) return;

    // dense fill: position s_qp[e]+s <- packed (e, slot)
    for (int p = tid; p < CPC * SLOTQ; p += 128) {
        const int e = p >> 5, s = p & 31;
        const int ce = s_qp[e + 1] - s_qp[e];
        if (s < ce) s_q[s_qp[e] + s] = (e << 5) | s;
    }
    __syncthreads();

    const float r  = radius[0];
    const float r2 = __fmul_rn(r, r);
    int reach = (int)ceilf(r * (float)GRIDW);
    if (reach < 1) reach = 1;

    for (int qi = group; qi < ncta; qi += 32) {
        const int pk   = s_q[qi];
        const int gcell = cell0 + (pk >> 5);
        const int slot  = pk & 31;
        const int b = gcell / NCELLS;
        const int c = gcell - b * NCELLS;
        const int cx = c % GRIDW, cy = c / GRIDW;

        const float4 qv = g_qslots[(size_t)gcell * SLOTQ + slot];
        const float q0 = qv.x, q1 = qv.y, qn = qv.z;
        const int   oq = __float_as_int(qv.w);

        unsigned short* myreg = s_reg + tid * RSTR;
        int mycnt = 0;

        if (reach == 1) {
            // prefetch 9 headers (independent LDGs)
            int hbase[9], hcnt[9];
            #pragma unroll
            for (int dy = -1; dy <= 1; ++dy) {
                #pragma unroll
                for (int dx = -1; dx <= 1; ++dx) {
                    const int gx = cx + dx, gy = cy + dy;
                    const bool ok = (gx >= 0) & (gx < GRIDW) & (gy >= 0) & (gy < GRIDW);
                    const int cc = b * NCELLS + gy * GRIDW + gx;
                    const int e9 = 3 * (dy + 1) + (dx + 1);
                    hbase[e9] = cc * SLOTC;
                    int nv = ok ? g_ccnt[cc] : 0;
                    hcnt[e9] = nv < SLOTC ? nv : SLOTC;
                }
            }
            #pragma unroll
            for (int e9 = 0; e9 < 9; ++e9) {
                const float4* cp = g_slots + hbase[e9];
                for (int t = sub; t < hcnt[e9]; t += 4) {
                    const float4 p = cp[t];
                    // cross = RN(RN(q0*px)+RN(q1*py)); 2*cross exact (self-add)
                    const float cr = __fadd_rn(__fmul_rn(q0, p.x), __fmul_rn(q1, p.y));
                    // v = RN(RN(qn + dn) - 2*cross)
                    const float v  = __fsub_rn(__fadd_rn(qn, p.z), __fadd_rn(cr, cr));
                    if (v <= r2) {
                        if (mycnt < RCAP)
                            myreg[mycnt] = (unsigned short)__float_as_int(p.w);
                        mycnt++;
                    }
                }
            }
        } else {
            // generic path (not taken for r=0.03)
            const int x0 = max(0, cx - reach), x1 = min(GRIDW - 1, cx + reach);
            const int y0 = max(0, cy - reach), y1 = min(GRIDW - 1, cy + reach);
            for (int gy = y0; gy <= y1; ++gy)
                for (int gx = x0; gx <= x1; ++gx) {
                    const int cc = b * NCELLS + gy * GRIDW + gx;
                    int nv = g_ccnt[cc]; nv = nv < SLOTC ? nv : SLOTC;
                    const float4* cp = g_slots + (size_t)cc * SLOTC;
                    for (int t = sub; t < nv; t += 4) {
                        const float4 p = cp[t];
                        const float cr = __fadd_rn(__fmul_rn(q0, p.x), __fmul_rn(q1, p.y));
                        const float v  = __fsub_rn(__fadd_rn(qn, p.z), __fadd_rn(cr, cr));
                        if (v <= r2) {
                            if (mycnt < RCAP)
                                myreg[mycnt] = (unsigned short)__float_as_int(p.w);
                            mycnt++;
                        }
                    }
                }
        }

        // group totals (4-lane shfl gather; group-uniform results)
        const int l0 = __shfl_sync(0xFFFFFFFFu, mycnt, lb + 0);
        const int l1 = __shfl_sync(0xFFFFFFFFu, mycnt, lb + 1);
        const int l2 = __shfl_sync(0xFFFFFFFFu, mycnt, lb + 2);
        const int l3 = __shfl_sync(0xFFFFFFFFu, mycnt, lb + 3);
        const int cnt = l0 + l1 + l2 + l3;
        const int k = cnt < MAXN ? cnt : MAXN;

        float* out = nbr_idx + (size_t)(b * NQ + oq) * MAXN;
        for (int s = k + sub; s < MAXN; s += 4) out[s] = -1.0f;

        // rank-selection emit across the group's 4 regions: rank(v) =
        // #{u in accepted set : u < v}. Set-based -> deterministic, sorted.
        const int n0 = l0 < RCAP ? l0 : RCAP;
        const int n1 = l1 < RCAP ? l1 : RCAP;
        const int n2 = l2 < RCAP ? l2 : RCAP;
        const int n3 = l3 < RCAP ? l3 : RCAP;
        const unsigned short* r0 = s_reg + (tb + 0) * RSTR;
        const unsigned short* r1 = s_reg + (tb + 1) * RSTR;
        const unsigned short* r2p = s_reg + (tb + 2) * RSTR;
        const unsigned short* r3 = s_reg + (tb + 3) * RSTR;

        const int myn = mycnt < RCAP ? mycnt : RCAP;
        for (int j = 0; j < myn; ++j) {
            const unsigned short v = myreg[j];
            int rank = 0;
            for (int t = 0; t < n0; ++t) rank += (r0[t] < v);
            for (int t = 0; t < n1; ++t) rank += (r1[t] < v);
            for (int t = 0; t < n2; ++t) rank += (r2p[t] < v);
            for (int t = 0; t < n3; ++t) rank += (r3[t] < v);
            if (rank < MAXN) out[rank] = (float)v;
        }

        if (sub == 0) g_counts[b * NQ + oq] = cnt;
    }
}

// ---- launch 3: row_splits + counter reset ----
__global__ void __launch_bounds__(1024)
row_splits_kernel(float* __restrict__ row_splits)
{
    __shared__ int warp_sums[32];
    const int b = blockIdx.x;
    const int t = threadIdx.x;
    const int lane = t & 31, wid = t >> 5;

    // reset slotted-cell cursors for the next graph replay
    {
        const int i = b * 1024 + t;                  // 0..8191
        if (i < BATCH * NCELLS) { g_ccnt[i] = 0; g_qcnt[i] = 0; }
        const int i2 = i + BATCH * 1024;
        if (i2 < BATCH * NCELLS) { g_ccnt[i2] = 0; g_qcnt[i2] = 0; }
    }

    const int* c = g_counts + b * NQ;
    const int base = t * 4;
    const int c0 = c[base + 0], c1 = c[base + 1], c2 = c[base + 2], c3 = c[base + 3];
    const int s0 = c0, s1 = s0 + c1, s2 = s1 + c2, s3 = s2 + c3;
    const int total = s3;

    int x = total;
    #pragma unroll
    for (int o = 1; o < 32; o <<= 1) {
        int y = __shfl_up_sync(0xFFFFFFFFu, x, o);
        if (lane >= o) x += y;
    }
    if (lane == 31) warp_sums[wid] = x;
    __syncthreads();
    if (wid == 0) {
        int w = warp_sums[lane];
        #pragma unroll
        for (int o = 1; o < 32; o <<= 1) {
            int y = __shfl_up_sync(0xFFFFFFFFu, w, o);
            if (lane >= o) w += y;
        }
        warp_sums[lane] = w;
    }
    __syncthreads();

    const int excl = (x - total) + (wid > 0 ? warp_sums[wid - 1] : 0);
    float* rs = row_splits + b * (NQ + 1);
    if (t == 0) rs[0] = 0.0f;
    rs[base + 1] = (float)(excl + s0);
    rs[base + 2] = (float)(excl + s1);
    rs[base + 3] = (float)(excl + s2);
    rs[base + 4] = (float)(excl + s3);
}

extern "C" void kernel_launch(void* const* d_in, const int* in_sizes, int n_in,
                              void* d_out, int out_size)
{
    const float* data    = (const float*)d_in[0];   // [8, 9225, 2]
    const float* queries = (const float*)d_in[1];   // [8, 4096, 2]
    const float* radius  = (const float*)d_in[2];   // scalar

    float* nbr_idx    = (float*)d_out;                          // [8, 4096, 64]
    float* row_splits = nbr_idx + (size_t)BATCH * NQ * MAXN;    // [8, 4097]

    scatter_kernel<<<(BATCH * NPTS + 255) / 256, 256>>>(data, queries);
    query_kernel<<<(BATCH * NCELLS) / CPC, 128>>>(radius, nbr_idx);
    row_splits_kernel<<<BATCH, 1024>>>(row_splits);
}

// round 12
// speedup vs baseline: 1.1897x; 1.1897x over previous
#include <cuda_runtime.h>
#include <cuda_bf16.h>

// NeighborSearch_batch: slotted 33x33 grid (data+queries) -> dense query
// compaction -> 4-lane-group accept (R6 structure) + warp-cooperative
// rank emit -> row_splits. 4 launches.
// B=8, n=9225, m=4096, d=2, r=0.03.
// Output (float32): neighbors_index [B,m,64] then row_splits [B,m+1].

#define BATCH  8
#define NPTS   9225
#define NQ     4096
#define MAXN   64
#define GRIDW  33
#define NCELLS (GRIDW * GRIDW)        // 1089
#define SLOTC  48                     // data slots/cell  (lambda 8.5)
#define SLOTQ  32                     // query slots/cell (lambda 3.8)
#define CSTR   66                     // cand row stride in u16 (33 words)

#define LPQ    4                      // lanes per query
#define QPB    32                     // queries per CTA
#define QTPB   (LPQ * QPB)            // 128 threads

// zero-initialized at module load; counters re-zeroed at end of each run
__device__ int    g_ccnt  [BATCH * NCELLS];
__device__ int    g_qcnt  [BATCH * NCELLS];
__device__ float4 g_slots [BATCH * NCELLS * SLOTC];  // (x, y, dn, idx bits)
__device__ float4 g_qslots[BATCH * NCELLS * SLOTQ];  // (x, y, qn, idx bits)
__device__ float4 g_qpts  [BATCH * NQ];              // dense, cell-sorted
__device__ int    g_counts[BATCH * NQ];

__device__ __forceinline__ int clampi(int v, int lo, int hi) {
    return v < lo ? lo : (v > hi ? hi : v);
}

// ---- launch 1: scatter data AND queries into slotted cells ----
__global__ void scatter_kernel(const float* __restrict__ data,
                               const float* __restrict__ queries)
{
    const int gt = blockIdx.x * blockDim.x + threadIdx.x;
    if (gt < BATCH * NPTS) {
        const int b = gt / NPTS;
        const int j = gt - b * NPTS;
        const float2 pf = ((const float2*)data)[gt];
        // dn = RN(RN(x*x) + RN(y*y))  (matches jnp.sum(data*data))
        const float nn = __fadd_rn(__fmul_rn(pf.x, pf.x), __fmul_rn(pf.y, pf.y));
        const int cx = clampi((int)(pf.x * (float)GRIDW), 0, GRIDW - 1);
        const int cy = clampi((int)(pf.y * (float)GRIDW), 0, GRIDW - 1);
        const int c = b * NCELLS + cy * GRIDW + cx;
        const int pos = atomicAdd(&g_ccnt[c], 1);
        if (pos < SLOTC)
            g_slots[(size_t)c * SLOTC + pos] = make_float4(pf.x, pf.y, nn, __int_as_float(j));
    }
    if (gt < BATCH * NQ) {
        const int b = gt >> 12;
        const int j = gt & (NQ - 1);
        const float2 qf = ((const float2*)queries)[gt];
        const float nn = __fadd_rn(__fmul_rn(qf.x, qf.x), __fmul_rn(qf.y, qf.y));
        const int cx = clampi((int)(qf.x * (float)GRIDW), 0, GRIDW - 1);
        const int cy = clampi((int)(qf.y * (float)GRIDW), 0, GRIDW - 1);
        const int c = b * NCELLS + cy * GRIDW + cx;
        const int pos = atomicAdd(&g_qcnt[c], 1);
        if (pos < SLOTQ)
            g_qslots[(size_t)c * SLOTQ + pos] = make_float4(qf.x, qf.y, nn, __int_as_float(j));
    }
}

// ---- launch 2: compact slotted queries into dense cell-sorted g_qpts ----
__global__ void __launch_bounds__(1024)
qcompact_kernel()
{
    __shared__ int warp_sums[32];
    __shared__ int s_start[NCELLS + 1];

    const int b = blockIdx.x;
    const int t = threadIdx.x;
    const int lane = t & 31, wid = t >> 5;
    const int i0 = 2 * t, i1 = 2 * t + 1;

    int c0 = 0, c1 = 0;
    if (i0 < NCELLS) { c0 = g_qcnt[b * NCELLS + i0]; c0 = c0 < SLOTQ ? c0 : SLOTQ; }
    if (i1 < NCELLS) { c1 = g_qcnt[b * NCELLS + i1]; c1 = c1 < SLOTQ ? c1 : SLOTQ; }
    const int total = c0 + c1;

    int x = total;
    #pragma unroll
    for (int o = 1; o < 32; o <<= 1) {
        int y = __shfl_up_sync(0xFFFFFFFFu, x, o);
        if (lane >= o) x += y;
    }
    if (lane == 31) warp_sums[wid] = x;
    __syncthreads();
    if (wid == 0) {
        int w = warp_sums[lane];
        #pragma unroll
        for (int o = 1; o < 32; o <<= 1) {
            int y = __shfl_up_sync(0xFFFFFFFFu, w, o);
            if (lane >= o) w += y;
        }
        warp_sums[lane] = w;
    }
    __syncthreads();

    const int excl = (x - total) + (wid > 0 ? warp_sums[wid - 1] : 0);
    if (i0 < NCELLS) s_start[i0] = excl;
    if (i1 < NCELLS) s_start[i1] = excl + c0;
    __syncthreads();

    // copy: thread handles cells t and t+1024
    for (int c = t; c < NCELLS; c += 1024) {
        int nc = g_qcnt[b * NCELLS + c]; nc = nc < SLOTQ ? nc : SLOTQ;
        const float4* src = g_qslots + (size_t)(b * NCELLS + c) * SLOTQ;
        float4* dst = g_qpts + (size_t)b * NQ + s_start[c];
        for (int s = 0; s < nc; ++s) dst[s] = src[s];
    }
}

// ---- launch 3: query kernel ----
// 4-lane groups over dense cell-sorted queries (R6-proven accept loop,
// slotted cells, 9 prefetched headers), warp-cooperative rank emit.
__global__ void __launch_bounds__(QTPB)
query_kernel(const float* __restrict__ radius,
             float* __restrict__ nbr_idx)
{
    __shared__ unsigned short s_cand[QPB][CSTR];
    __shared__ int s_cnt[QPB];
    __shared__ int s_oq [QPB];

    const int tid   = threadIdx.x;
    const int sub   = tid & (LPQ - 1);
    const int qslot = tid >> 2;               // 0..31
    const int lane  = tid & 31;
    const int shift = lane & ~(LPQ - 1);
    const unsigned gmask = 0xFu << shift;

    const int b = blockIdx.y;

    const float4 qv = g_qpts[(size_t)b * NQ + blockIdx.x * QPB + qslot];
    const float q0 = qv.x, q1 = qv.y, qn = qv.z;
    const int   oq = __float_as_int(qv.w);

    const float r  = radius[0];
    const float r2 = __fmul_rn(r, r);
    int reach = (int)ceilf(r * (float)GRIDW);
    if (reach < 1) reach = 1;

    const int cx = clampi((int)(q0 * (float)GRIDW), 0, GRIDW - 1);
    const int cy = clampi((int)(q1 * (float)GRIDW), 0, GRIDW - 1);

    int cnt = 0;

    if (reach == 1) {
        // prefetch 9 headers (independent LDGs, group-uniform values)
        int hbase[9], hcnt[9];
        #pragma unroll
        for (int dy = -1; dy <= 1; ++dy) {
            #pragma unroll
            for (int dx = -1; dx <= 1; ++dx) {
                const int gx = cx + dx, gy = cy + dy;
                const bool ok = (gx >= 0) & (gx < GRIDW) & (gy >= 0) & (gy < GRIDW);
                const int cc = b * NCELLS + gy * GRIDW + gx;
                const int e = 3 * (dy + 1) + (dx + 1);
                hbase[e] = cc * SLOTC;
                int nv = ok ? g_ccnt[cc] : 0;
                hcnt[e] = nv < SLOTC ? nv : SLOTC;
            }
        }
        #pragma unroll
        for (int e = 0; e < 9; ++e) {
            const float4* cp = g_slots + hbase[e];
            const int nc = hcnt[e];
            for (int ib = 0; ib < nc; ib += LPQ) {
                const int i = ib + sub;
                bool acc = false;
                int idx = 0;
                if (i < nc) {
                    const float4 p = cp[i];
                    // cross = RN(RN(q0*px)+RN(q1*py)); 2*cross exact (self-add)
                    const float cr = __fadd_rn(__fmul_rn(q0, p.x), __fmul_rn(q1, p.y));
                    // v = RN(RN(qn + dn) - 2*cross)
                    const float v  = __fsub_rn(__fadd_rn(qn, p.z), __fadd_rn(cr, cr));
                    acc = (v <= r2);
                    idx = __float_as_int(p.w);
                }
                const unsigned bal = __ballot_sync(gmask, acc);
                const unsigned nib = (bal >> shift) & 0xFu;
                if (acc) {
                    const int s = cnt + __popc(nib & ((1u << sub) - 1u));
                    if (s < MAXN) s_cand[qslot][s] = (unsigned short)idx;
                }
                cnt += __popc(nib);
            }
        }
    } else {
        // generic path (not taken for r=0.03)
        const int x0 = max(0, cx - reach), x1 = min(GRIDW - 1, cx + reach);
        const int y0 = max(0, cy - reach), y1 = min(GRIDW - 1, cy + reach);
        for (int gy = y0; gy <= y1; ++gy)
            for (int gx = x0; gx <= x1; ++gx) {
                const int cc = b * NCELLS + gy * GRIDW + gx;
                int nc = g_ccnt[cc]; nc = nc < SLOTC ? nc : SLOTC;
                const float4* cp = g_slots + (size_t)cc * SLOTC;
                for (int ib = 0; ib < nc; ib += LPQ) {
                    const int i = ib + sub;
                    bool acc = false;
                    int idx = 0;
                    if (i < nc) {
                        const float4 p = cp[i];
                        const float cr = __fadd_rn(__fmul_rn(q0, p.x), __fmul_rn(q1, p.y));
                        const float v  = __fsub_rn(__fadd_rn(qn, p.z), __fadd_rn(cr, cr));
                        acc = (v <= r2);
                        idx = __float_as_int(p.w);
                    }
                    const unsigned bal = __ballot_sync(gmask, acc);
                    const unsigned nib = (bal >> shift) & 0xFu;
                    if (acc) {
                        const int s = cnt + __popc(nib & ((1u << sub) - 1u));
                        if (s < MAXN) s_cand[qslot][s] = (unsigned short)idx;
                    }
                    cnt += __popc(nib);
                }
            }
    }

    if (sub == 0) { s_cnt[qslot] = cnt; s_oq[qslot] = oq; }
    __syncwarp();

    // warp-cooperative emit: process the warp's 8 queries in turn.
    // lane i takes candidate i (and i+32); rank counted against an
    // LDS-broadcast stream of all k candidates. Set-based -> deterministic.
    const int wqb = (tid >> 5) << 3;   // first qslot of this warp
    #pragma unroll
    for (int qq = 0; qq < 8; ++qq) {
        const int qs  = wqb + qq;
        const int cq  = s_cnt[qs];
        const int k   = cq < MAXN ? cq : MAXN;
        float* out = nbr_idx + (size_t)(b * NQ + s_oq[qs]) * MAXN;

        for (int s = k + lane; s < MAXN; s += 32) out[s] = -1.0f;

        int v0 = -1, v1 = -1, r0 = 0, r1 = 0;
        const bool a0 = lane < k, a1 = lane + 32 < k;
        if (a0) v0 = s_cand[qs][lane];
        if (a1) v1 = s_cand[qs][lane + 32];
        for (int j = 0; j < k; ++j) {
            const int u = s_cand[qs][j];   // broadcast
            r0 += (u < v0);
            r1 += (u < v1);
        }
        if (a0) out[r0] = (float)v0;
        if (a1) out[r1] = (float)v1;
        if (lane == 0) g_counts[b * NQ + s_oq[qs]] = cq;
    }
}

// ---- launch 4: row_splits + counter reset ----
__global__ void __launch_bounds__(1024)
row_splits_kernel(float* __restrict__ row_splits)
{
    __shared__ int warp_sums[32];
    const int b = blockIdx.x;
    const int t = threadIdx.x;
    const int lane = t & 31, wid = t >> 5;

    // reset slotted-cell cursors for the next graph replay
    {
        const int i = b * 1024 + t;                  // 0..8191
        if (i < BATCH * NCELLS) { g_ccnt[i] = 0; g_qcnt[i] = 0; }
        const int i2 = i + BATCH * 1024;
        if (i2 < BATCH * NCELLS) { g_ccnt[i2] = 0; g_qcnt[i2] = 0; }
    }

    const int* c = g_counts + b * NQ;
    const int base = t * 4;
    const int c0 = c[base + 0], c1 = c[base + 1], c2 = c[base + 2], c3 = c[base + 3];
    const int s0 = c0, s1 = s0 + c1, s2 = s1 + c2, s3 = s2 + c3;
    const int total = s3;

    int x = total;
    #pragma unroll
    for (int o = 1; o < 32; o <<= 1) {
        int y = __shfl_up_sync(0xFFFFFFFFu, x, o);
        if (lane >= o) x += y;
    }
    if (lane == 31) warp_sums[wid] = x;
    __syncthreads();
    if (wid == 0) {
        int w = warp_sums[lane];
        #pragma unroll
        for (int o = 1; o < 32; o <<= 1) {
            int y = __shfl_up_sync(0xFFFFFFFFu, w, o);
            if (lane >= o) w += y;
        }
        warp_sums[lane] = w;
    }
    __syncthreads();

    const int excl = (x - total) + (wid > 0 ? warp_sums[wid - 1] : 0);
    float* rs = row_splits + b * (NQ + 1);
    if (t == 0) rs[0] = 0.0f;
    rs[base + 1] = (float)(excl + s0);
    rs[base + 2] = (float)(excl + s1);
    rs[base + 3] = (float)(excl + s2);
    rs[base + 4] = (float)(excl + s3);
}

extern "C" void kernel_launch(void* const* d_in, const int* in_sizes, int n_in,
                              void* d_out, int out_size)
{
    const float* data    = (const float*)d_in[0];   // [8, 9225, 2]
    const float* queries = (const float*)d_in[1];   // [8, 4096, 2]
    const float* radius  = (const float*)d_in[2];   // scalar

    float* nbr_idx    = (float*)d_out;                          // [8, 4096, 64]
    float* row_splits = nbr_idx + (size_t)BATCH * NQ * MAXN;    // [8, 4097]

    scatter_kernel<<<(BATCH * NPTS + 255) / 256, 256>>>(data, queries);
    qcompact_kernel<<<BATCH, 1024>>>();

    dim3 qgrid(NQ / QPB, BATCH);
    query_kernel<<<qgrid, QTPB>>>(radius, nbr_idx);
    row_splits_kernel<<<BATCH, 1024>>>(row_splits);
}

// round 13
// speedup vs baseline: 1.4104x; 1.1855x over previous
#include <cuda_runtime.h>
#include <cuda_bf16.h>

// NeighborSearch_batch via 33x33 uniform grid (R6 configuration, measured
// best) with row_splits fused into the query kernel via done-counters.
// Fused single-CTA-per-batch binning, 4-lanes-per-query search,
// rank-selection emit (deterministic, sorted, no sort).
// B=8, n=9225 data pts, m=4096 queries, d=2, radius=0.03
// Output (float32): neighbors_index [B, m, 64] then row_splits [B, m+1].

#define BATCH  8
#define NPTS   9225
#define NQ     4096
#define MAXN   64
#define GRID   33
#define NCELLS (GRID * GRID)
#define CAP    64     // per-query accept capacity (reference: observed max ~50)

#define LPQ    4      // lanes per query
#define QPB    32     // queries per CTA
#define QTPB   (LPQ * QPB)   // 128 threads
#define CTAS_PER_B (NQ / QPB)  // 128 query CTAs per batch

// data binning (global, read by query kernel)
__device__ int    g_cnt_cell[BATCH * NCELLS];
__device__ int    g_start   [BATCH * NCELLS];
__device__ float4 g_pts     [BATCH * NPTS];   // (x, y, dn, idx-as-float-bits)
// binned queries: (x, y, qn, orig-idx-as-float-bits)
__device__ float4 g_qpts    [BATCH * NQ];
// per-query neighbor counts (original query order)
__device__ int    g_counts  [BATCH * NQ];
// per-batch done counters (monotone; never reset -> graph-replay safe)
__device__ unsigned int g_done[BATCH];

__device__ __forceinline__ int cell_of(float x, float y) {
    int cx = (int)(x * (float)GRID); if (cx > GRID - 1) cx = GRID - 1; if (cx < 0) cx = 0;
    int cy = (int)(y * (float)GRID); if (cy > GRID - 1) cy = GRID - 1; if (cy < 0) cy = 0;
    return cy * GRID + cx;
}

__device__ __forceinline__ int ldcg_i32(const int* p) {
    int v;
    asm volatile("ld.global.cg.s32 %0, [%1];" : "=r"(v) : "l"(p));
    return v;
}

// One CTA per (batch, kind): blocks 0..7 bin data, 8..15 bin queries.
// Count (smem atomics) -> block scan (1089) -> scatter (smem cursors).
__global__ void __launch_bounds__(1024)
bin_kernel(const float* __restrict__ data,
           const float* __restrict__ queries)
{
    __shared__ int scnt[NCELLS];
    __shared__ int scur[NCELLS];
    __shared__ int warp_sums[32];

    const int isq = blockIdx.x >= BATCH;
    const int b   = blockIdx.x - (isq ? BATCH : 0);
    const int n   = isq ? NQ : NPTS;
    const float* src = isq ? (queries + (size_t)b * NQ * 2)
                           : (data    + (size_t)b * NPTS * 2);
    float4* dst = isq ? (g_qpts + (size_t)b * NQ)
                      : (g_pts  + (size_t)b * NPTS);

    const int t = threadIdx.x;
    const int lane = t & 31, wid = t >> 5;

    for (int i = t; i < NCELLS; i += 1024) scnt[i] = 0;
    __syncthreads();

    // pass 1: count
    for (int i = t; i < n; i += 1024) {
        const float x = src[2 * i];
        const float y = src[2 * i + 1];
        atomicAdd(&scnt[cell_of(x, y)], 1);
    }
    __syncthreads();

    // exclusive block scan over NCELLS=1089 (2 elems/thread)
    const int i0 = 2 * t, i1 = 2 * t + 1;
    const int c0 = (i0 < NCELLS) ? scnt[i0] : 0;
    const int c1 = (i1 < NCELLS) ? scnt[i1] : 0;
    const int total = c0 + c1;

    int x = total;
    #pragma unroll
    for (int o = 1; o < 32; o <<= 1) {
        int y = __shfl_up_sync(0xFFFFFFFFu, x, o);
        if (lane >= o) x += y;
    }
    if (lane == 31) warp_sums[wid] = x;
    __syncthreads();
    if (wid == 0) {
        int w = warp_sums[lane];
        #pragma unroll
        for (int o = 1; o < 32; o <<= 1) {
            int y = __shfl_up_sync(0xFFFFFFFFu, w, o);
            if (lane >= o) w += y;
        }
        warp_sums[lane] = w;
    }
    __syncthreads();

    const int excl = (x - total) + (wid > 0 ? warp_sums[wid - 1] : 0);
    if (i0 < NCELLS) {
        scur[i0] = excl;
        if (!isq) { g_start[b * NCELLS + i0] = excl; g_cnt_cell[b * NCELLS + i0] = c0; }
    }
    if (i1 < NCELLS) {
        scur[i1] = excl + c0;
        if (!isq) { g_start[b * NCELLS + i1] = excl + c0; g_cnt_cell[b * NCELLS + i1] = c1; }
    }
    __syncthreads();

    // pass 2: scatter (norm term computed with reference rounding:
    // nn = RN(RN(x*x) + RN(y*y)) matches jnp.sum(v*v, axis=-1))
    for (int i = t; i < n; i += 1024) {
        const float px = src[2 * i];
        const float py = src[2 * i + 1];
        const float nn = __fadd_rn(__fmul_rn(px, px), __fmul_rn(py, py));
        const int c = cell_of(px, py);
        const int pos = atomicAdd(&scur[c], 1);
        dst[pos] = make_float4(px, py, nn, __int_as_float(i));
    }
}

// 4 lanes cooperate on one query: split candidate segments, ballot-compact
// accepts into smem, rank-selection emit (order-independent => deterministic).
// The last CTA of each batch (monotone done-counter) computes row_splits.
__global__ void __launch_bounds__(QTPB)
query_kernel(const float* __restrict__ radius,
             float* __restrict__ nbr_idx,
             float* __restrict__ row_splits)
{
    __shared__ int cand[CAP][QPB + 1];   // stride 33: conflict-free
    __shared__ int s_scan[4];
    __shared__ int s_last;

    const int tid   = threadIdx.x;
    const int sub   = tid & (LPQ - 1);       // 0..3 within group
    const int qslot = tid >> 2;               // 0..31 query slot in CTA
    const int shift = (tid & 31) & ~(LPQ - 1);
    const unsigned gmask = 0xFu << shift;

    const int b = blockIdx.y;
    const int qbin = blockIdx.x * QPB + qslot;

    const float4 qv = g_qpts[(size_t)b * NQ + qbin];  // 4-lane broadcast
    const float q0 = qv.x;
    const float q1 = qv.y;
    const float qn = qv.z;
    const int   oq = __float_as_int(qv.w);

    const float r  = radius[0];
    const float r2 = __fmul_rn(r, r);
    int reach = (int)ceilf(r * (float)GRID);
    if (reach < 1) reach = 1;

    int cx = (int)(q0 * (float)GRID); if (cx > GRID - 1) cx = GRID - 1; if (cx < 0) cx = 0;
    int cy = (int)(q1 * (float)GRID); if (cy > GRID - 1) cy = GRID - 1; if (cy < 0) cy = 0;
    const int x0 = max(0, cx - reach), x1 = min(GRID - 1, cx + reach);
    const int y0 = max(0, cy - reach), y1 = min(GRID - 1, cy + reach);

    const float4* pts = g_pts + (size_t)b * NPTS;
    const int* starts = g_start    + b * NCELLS;
    const int* cnts   = g_cnt_cell + b * NCELLS;

    int cnt = 0;

    for (int gy = y0; gy <= y1; ++gy) {
        const int ca = gy * GRID + x0;
        const int cb = gy * GRID + x1;
        const int s = starts[ca];
        const int e = starts[cb] + cnts[cb];
        // group-uniform trip count; lanes take i = ib+sub (coalesced 64B)
        for (int ib = s; ib < e; ib += LPQ) {
            const int i = ib + sub;
            bool acc = false;
            int idx = 0;
            if (i < e) {
                const float4 p = pts[i];
                // cross = RN(RN(q0*px) + RN(q1*py)); 2*cross exact (self-add)
                const float cr = __fadd_rn(__fmul_rn(q0, p.x), __fmul_rn(q1, p.y));
                // v = RN(RN(qn + dn) - 2*cross)
                const float v  = __fsub_rn(__fadd_rn(qn, p.z), __fadd_rn(cr, cr));
                acc = (v <= r2);
                idx = __float_as_int(p.w);
            }
            const unsigned bal = __ballot_sync(gmask, acc);
            const unsigned nib = (bal >> shift) & 0xFu;
            if (acc) {
                const int s2 = cnt + __popc(nib & ((1u << sub) - 1u));
                if (s2 < CAP) cand[s2][qslot] = idx;
            }
            cnt += __popc(nib);
        }
    }

    float* out = nbr_idx + ((size_t)(b * NQ + oq)) * MAXN;
    const int k = cnt < CAP ? cnt : CAP;

    // -1 fill (slots k..63), split across the 4 lanes
    for (int s = k + sub; s < MAXN; s += LPQ) out[s] = -1.0f;

    // rank-selection emit: rank_i = #{j : v_j < v_i} is a permutation of
    // 0..k-1 (indices distinct) -> sorted output, scatter-order independent.
    for (int i = sub; i < k; i += LPQ) {
        const int v = cand[i][qslot];
        int rank = 0;
        #pragma unroll 4
        for (int j = 0; j < k; ++j)
            rank += (cand[j][qslot] < v) ? 1 : 0;
        out[rank] = (float)v;   // rank <= k-1 < MAXN <= CAP
    }

    if (sub == 0) g_counts[b * NQ + oq] = cnt;

    // ---- fused row_splits: last CTA of this batch does the scan ----
    __threadfence();
    __syncthreads();
    if (tid == 0) {
        const unsigned t = atomicAdd(&g_done[b], 1u);
        s_last = ((t % CTAS_PER_B) == (CTAS_PER_B - 1)) ? 1 : 0;
    }
    __syncthreads();
    if (!s_last) return;

    // this CTA: compute row_splits for batch b (counts read via L2)
    {
        const int lane = tid & 31, wid = tid >> 5;
        const int* cc = g_counts + b * NQ;
        const int base = tid * 32;

        int vals[32];
        int tot = 0;
        #pragma unroll 8
        for (int i = 0; i < 32; ++i) {
            vals[i] = ldcg_i32(cc + base + i);
            tot += vals[i];
        }

        int x2 = tot;
        #pragma unroll
        for (int o = 1; o < 32; o <<= 1) {
            const int y = __shfl_up_sync(0xFFFFFFFFu, x2, o);
            if (lane >= o) x2 += y;
        }
        if (lane == 31) s_scan[wid] = x2;
        __syncthreads();
        if (wid == 0 && lane < 4) {
            int w = s_scan[lane];
            #pragma unroll
            for (int o = 1; o < 4; o <<= 1) {
                const int y = __shfl_up_sync(0x0000000Fu, w, o);
                if (lane >= o) w += y;
            }
            s_scan[lane] = w;
        }
        __syncthreads();

        int run = (x2 - tot) + (wid > 0 ? s_scan[wid - 1] : 0);
        float* rs = row_splits + b * (NQ + 1);
        if (tid == 0) rs[0] = 0.0f;
        #pragma unroll 8
        for (int i = 0; i < 32; ++i) {
            run += vals[i];
            rs[base + 1 + i] = (float)run;
        }
    }
}

extern "C" void kernel_launch(void* const* d_in, const int* in_sizes, int n_in,
                              void* d_out, int out_size)
{
    const float* data    = (const float*)d_in[0];   // [8, 9225, 2]
    const float* queries = (const float*)d_in[1];   // [8, 4096, 2]
    const float* radius  = (const float*)d_in[2];   // scalar

    float* nbr_idx    = (float*)d_out;                          // [8, 4096, 64]
    float* row_splits = nbr_idx + (size_t)BATCH * NQ * MAXN;    // [8, 4097]

    bin_kernel<<<2 * BATCH, 1024>>>(data, queries);

    dim3 qgrid(NQ / QPB, BATCH);
    query_kernel<<<qgrid, QTPB>>>(radius, nbr_idx, row_splits);
}